// round 3
// baseline (speedup 1.0000x reference)
#include <cuda_runtime.h>
#include <cstdint>
#include <cstddef>

#define D 256
#define BKK 16
#define LDSW (BKK + 1)

// ---------------- device scratch (no allocations allowed) ----------------
__device__ float g_WcT[D * D];        // WcT[n][k] = sum_i Wq[i][k]*Wk[i][n]
__device__ float g_wv[D];             // wv[l] = sum_i bq[i]*Wk[i][l]
__device__ float g_G[32 * 256 * D];   // G = F_a @ Wc   [B*T, D]
__device__ float g_v[32 * 4096];      // v[b,s] = F_s[b,s] . wv

// ---------------- helpers ----------------
__device__ __forceinline__ uint32_t f2tf(float x) {
    uint32_t u;
    asm("cvt.rna.tf32.f32 %0, %1;" : "=r"(u) : "f"(x));
    return u;
}

__device__ __forceinline__ void mma8(float c[4], const uint32_t a[4], const uint32_t b[2]) {
    asm volatile(
        "mma.sync.aligned.m16n8k8.row.col.f32.tf32.tf32.f32 "
        "{%0,%1,%2,%3}, {%4,%5,%6,%7}, {%8,%9}, {%0,%1,%2,%3};"
        : "+f"(c[0]), "+f"(c[1]), "+f"(c[2]), "+f"(c[3])
        : "r"(a[0]), "r"(a[1]), "r"(a[2]), "r"(a[3]), "r"(b[0]), "r"(b[1]));
}

// ---------------- K1: Wc^T and wv ----------------
__global__ __launch_bounds__(D) void k_prep(const float* __restrict__ Wq,
                                            const float* __restrict__ Wk,
                                            const float* __restrict__ bq) {
    int n = blockIdx.x;
    int k = threadIdx.x;
    float acc = 0.f;
    for (int i = 0; i < D; ++i)
        acc = fmaf(Wq[i * D + k], Wk[i * D + n], acc);
    g_WcT[n * D + k] = acc;

    __shared__ float red[D];
    red[k] = bq[k] * Wk[k * D + n];
    __syncthreads();
    for (int s = D / 2; s > 0; s >>= 1) {
        if (k < s) red[k] += red[k + s];
        __syncthreads();
    }
    if (k == 0) g_wv[n] = red[0];
}

// ---------------- K_v: v[b,s] = F_s[b,s] . wv ----------------
__global__ __launch_bounds__(256) void k_v(const float* __restrict__ F_s) {
    __shared__ float swv[D];
    int tid = threadIdx.x;
    swv[tid] = g_wv[tid];
    __syncthreads();
    int r = blockIdx.x * 32 + (tid >> 3);  // global row 0..131071
    int l8 = tid & 7;
    const float4* row = reinterpret_cast<const float4*>(F_s + (size_t)r * D);
    const float4* wv4 = reinterpret_cast<const float4*>(swv);
    float s = 0.f;
#pragma unroll
    for (int q = 0; q < 8; ++q) {
        float4 f = row[l8 * 8 + q];
        float4 w = wv4[l8 * 8 + q];
        s += f.x * w.x + f.y * w.y + f.z * w.z + f.w * w.w;
    }
    s += __shfl_down_sync(0xffffffffu, s, 4, 8);
    s += __shfl_down_sync(0xffffffffu, s, 2, 8);
    s += __shfl_down_sync(0xffffffffu, s, 1, 8);
    if (l8 == 0) g_v[r] = s;
}

// ---------------- generic split-tf32 GEMM: C[m,n] = sum_k A[m,k]*Bt[n,k] ----------------
// 128x128 tile per CTA, 256 threads (8 warps, 4x2), m16n8k8 tf32 mma.sync.
// BKK=16 keeps all smem configs below the 48KB default (no func attributes needed).
template <int ASPLIT, int BSPLIT, int LOGITS>
__global__ __launch_bounds__(256) void gemm_k(
    const float* __restrict__ A0, const float* __restrict__ B0, float* __restrict__ C0,
    size_t sA, size_t sB, size_t sC, int ldC,
    const float* __restrict__ v0, const int* __restrict__ msk0) {
    extern __shared__ uint32_t sm[];
    uint32_t* Ah = sm;
    uint32_t* Al = Ah + 128 * LDSW;                    // valid only if ASPLIT
    uint32_t* Bh = Ah + (1 + ASPLIT) * 128 * LDSW;
    uint32_t* Bl = Bh + 128 * LDSW;                    // valid only if BSPLIT

    int z = blockIdx.z;
    int m0 = blockIdx.y * 128;
    int n0 = blockIdx.x * 128;
    const float* A = A0 + z * sA + (size_t)m0 * D;
    const float* B = B0 + z * sB + (size_t)n0 * D;

    int tid = threadIdx.x;
    int lane = tid & 31, wid = tid >> 5;
    int g = lane >> 2, tg = lane & 3;
    int wm = (wid & 3) * 32;
    int wn = (wid >> 2) * 64;

    float acc[2][8][4];
#pragma unroll
    for (int i = 0; i < 2; ++i)
#pragma unroll
        for (int j = 0; j < 8; ++j)
#pragma unroll
            for (int c = 0; c < 4; ++c) acc[i][j][c] = 0.f;

    for (int k0 = 0; k0 < D; k0 += BKK) {
        // load 128x16 tiles of A and B: 512 float4s each, 2 per thread
#pragma unroll
        for (int q = 0; q < 2; ++q) {
            int idx = tid + 256 * q;
            int row = idx >> 2;           // 4 float4-groups per 16-wide row
            int c4 = (idx & 3) * 4;
            float4 xa = *reinterpret_cast<const float4*>(A + (size_t)row * D + k0 + c4);
            float4 xb = *reinterpret_cast<const float4*>(B + (size_t)row * D + k0 + c4);
            float va[4] = {xa.x, xa.y, xa.z, xa.w};
            float vb[4] = {xb.x, xb.y, xb.z, xb.w};
#pragma unroll
            for (int j = 0; j < 4; ++j) {
                uint32_t h = f2tf(va[j]);
                Ah[row * LDSW + c4 + j] = h;
                if (ASPLIT) Al[row * LDSW + c4 + j] = f2tf(va[j] - __uint_as_float(h));
            }
#pragma unroll
            for (int j = 0; j < 4; ++j) {
                uint32_t h = f2tf(vb[j]);
                Bh[row * LDSW + c4 + j] = h;
                if (BSPLIT) Bl[row * LDSW + c4 + j] = f2tf(vb[j] - __uint_as_float(h));
            }
        }
        __syncthreads();
#pragma unroll
        for (int kk = 0; kk < BKK; kk += 8) {
            uint32_t ah[2][4], al[2][4], bh[8][2], bl[8][2];
#pragma unroll
            for (int mi = 0; mi < 2; ++mi) {
                int r = wm + mi * 16;
                ah[mi][0] = Ah[(r + g) * LDSW + kk + tg];
                ah[mi][1] = Ah[(r + g + 8) * LDSW + kk + tg];
                ah[mi][2] = Ah[(r + g) * LDSW + kk + tg + 4];
                ah[mi][3] = Ah[(r + g + 8) * LDSW + kk + tg + 4];
                if (ASPLIT) {
                    al[mi][0] = Al[(r + g) * LDSW + kk + tg];
                    al[mi][1] = Al[(r + g + 8) * LDSW + kk + tg];
                    al[mi][2] = Al[(r + g) * LDSW + kk + tg + 4];
                    al[mi][3] = Al[(r + g + 8) * LDSW + kk + tg + 4];
                }
            }
#pragma unroll
            for (int ni = 0; ni < 8; ++ni) {
                int r = wn + ni * 8 + g;
                bh[ni][0] = Bh[r * LDSW + kk + tg];
                bh[ni][1] = Bh[r * LDSW + kk + tg + 4];
                if (BSPLIT) {
                    bl[ni][0] = Bl[r * LDSW + kk + tg];
                    bl[ni][1] = Bl[r * LDSW + kk + tg + 4];
                }
            }
#pragma unroll
            for (int mi = 0; mi < 2; ++mi)
#pragma unroll
                for (int ni = 0; ni < 8; ++ni) {
                    mma8(acc[mi][ni], ah[mi], bh[ni]);
                    if (ASPLIT) mma8(acc[mi][ni], al[mi], bh[ni]);
                    if (BSPLIT) mma8(acc[mi][ni], ah[mi], bl[ni]);
                }
        }
        __syncthreads();
    }

    // epilogue
    if (LOGITS) {
        const float* v = v0 + (size_t)z * 4096;
        const int* mk = msk0 + (size_t)z * 4096;
        float* C = C0 + z * sC;
#pragma unroll
        for (int mi = 0; mi < 2; ++mi) {
#pragma unroll
            for (int h = 0; h < 2; ++h) {
                int row = m0 + wm + mi * 16 + g + h * 8;
#pragma unroll
                for (int ni = 0; ni < 8; ++ni) {
                    int col = n0 + wn + ni * 8 + 2 * tg;
                    float y0 = (acc[mi][ni][h * 2 + 0] + v[col]) * 0.0625f;
                    float y1 = (acc[mi][ni][h * 2 + 1] + v[col + 1]) * 0.0625f;
                    if (mk[col] == 0) y0 = -1e30f;
                    if (mk[col + 1] == 0) y1 = -1e30f;
                    *reinterpret_cast<float2*>(C + (size_t)row * ldC + col) = make_float2(y0, y1);
                }
            }
        }
    } else {
        float* C = C0;
#pragma unroll
        for (int mi = 0; mi < 2; ++mi) {
#pragma unroll
            for (int h = 0; h < 2; ++h) {
                int row = m0 + wm + mi * 16 + g + h * 8;
#pragma unroll
                for (int ni = 0; ni < 8; ++ni) {
                    int col = n0 + wn + ni * 8 + 2 * tg;
                    *reinterpret_cast<float2*>(C + (size_t)row * ldC + col) =
                        make_float2(acc[mi][ni][h * 2 + 0], acc[mi][ni][h * 2 + 1]);
                }
            }
        }
    }
}

// ---------------- softmax over rows of 4096 (in-place on d_out) ----------------
__global__ __launch_bounds__(256) void k_softmax(float* __restrict__ Out) {
    size_t row = blockIdx.x;
    float* p = Out + row * 4096;
    int tid = threadIdx.x;
    float4 x[4];
#pragma unroll
    for (int q = 0; q < 4; ++q) x[q] = reinterpret_cast<float4*>(p)[tid + 256 * q];

    float mx = -3.0e38f;
#pragma unroll
    for (int q = 0; q < 4; ++q)
        mx = fmaxf(mx, fmaxf(fmaxf(x[q].x, x[q].y), fmaxf(x[q].z, x[q].w)));

    __shared__ float red[8];
    __shared__ float bc;
#pragma unroll
    for (int o = 16; o > 0; o >>= 1) mx = fmaxf(mx, __shfl_xor_sync(0xffffffffu, mx, o));
    if ((tid & 31) == 0) red[tid >> 5] = mx;
    __syncthreads();
    if (tid < 32) {
        float t = (tid < 8) ? red[tid] : -3.0e38f;
#pragma unroll
        for (int o = 4; o > 0; o >>= 1) t = fmaxf(t, __shfl_xor_sync(0xffffffffu, t, o));
        if (tid == 0) bc = t;
    }
    __syncthreads();
    mx = bc;

    float sum = 0.f;
#pragma unroll
    for (int q = 0; q < 4; ++q) {
        x[q].x = __expf(x[q].x - mx); sum += x[q].x;
        x[q].y = __expf(x[q].y - mx); sum += x[q].y;
        x[q].z = __expf(x[q].z - mx); sum += x[q].z;
        x[q].w = __expf(x[q].w - mx); sum += x[q].w;
    }
#pragma unroll
    for (int o = 16; o > 0; o >>= 1) sum += __shfl_xor_sync(0xffffffffu, sum, o);
    __syncthreads();
    if ((tid & 31) == 0) red[tid >> 5] = sum;
    __syncthreads();
    if (tid < 32) {
        float t = (tid < 8) ? red[tid] : 0.f;
#pragma unroll
        for (int o = 4; o > 0; o >>= 1) t += __shfl_xor_sync(0xffffffffu, t, o);
        if (tid == 0) bc = t;
    }
    __syncthreads();
    float inv = 1.0f / bc;
#pragma unroll
    for (int q = 0; q < 4; ++q) {
        x[q].x *= inv; x[q].y *= inv; x[q].z *= inv; x[q].w *= inv;
        reinterpret_cast<float4*>(p)[tid + 256 * q] = x[q];
    }
}

// ---------------- launch ----------------
extern "C" void kernel_launch(void* const* d_in, const int* in_sizes, int n_in,
                              void* d_out, int out_size) {
    const float* F_a = (const float*)d_in[0];
    const float* F_s = (const float*)d_in[1];
    const int*   M_s = (const int*)d_in[2];
    const float* Wq  = (const float*)d_in[3];
    const float* bq  = (const float*)d_in[4];
    const float* Wk  = (const float*)d_in[5];
    // d_in[6] (bk) is provably unused: it only contributes per-row constants,
    // which cancel in the softmax.
    float* out = (float*)d_out;

    void *p0 = nullptr, *p1 = nullptr, *p2 = nullptr;
    cudaGetSymbolAddress(&p0, g_WcT);
    cudaGetSymbolAddress(&p1, g_G);
    cudaGetSymbolAddress(&p2, g_v);
    float* pWcT = (float*)p0;
    float* pG = (float*)p1;
    float* pV = (float*)p2;

    const int smem_g = 4 * 128 * LDSW * 4;   // A hi/lo + B hi/lo = 34816 B
    const int smem_l = 3 * 128 * LDSW * 4;   // A hi/lo + B hi    = 26112 B

    // 1) Wc^T = (Wq^T Wk)^T and wv = Wk^T bq
    k_prep<<<D, D>>>(Wq, Wk, bq);

    // 2) G = F_a @ Wc   (M=8192, N=256, K=256), full split -> fp32-exact
    gemm_k<1, 1, 0><<<dim3(2, 64, 1), 256, smem_g>>>(
        F_a, pWcT, pG, 0, 0, 0, D, nullptr, nullptr);

    // 3) v[b,s] = F_s[b,s] . wv
    k_v<<<4096, 256>>>(F_s);

    // 4) logits = (G @ F_s^T + v) / 16, masked; written to d_out
    gemm_k<1, 0, 1><<<dim3(32, 2, 32), 256, smem_l>>>(
        pG, F_s, out,
        (size_t)(256 * D), (size_t)(4096 * D), (size_t)(256 * 4096), 4096,
        pV, M_s);

    // 5) row softmax in place
    k_softmax<<<32 * 256, 256>>>(out);
}

// round 4
// speedup vs baseline: 1.3409x; 1.3409x over previous
#include <cuda_runtime.h>
#include <cstdint>
#include <cstddef>

#define D 256
#define BKK 16
#define LDSW (BKK + 1)

// ---------------- device scratch (no allocations allowed) ----------------
__device__ float g_WcT[D * D];        // WcT[n][k] = sum_i Wq[i][k]*Wk[i][n]
__device__ float g_wv[D];             // wv[l] = sum_i bq[i]*Wk[i][l]
__device__ float g_G[32 * 256 * D];   // G = F_a @ Wc   [B*T, D]
__device__ float g_v[32 * 4096];      // v[b,s] = F_s[b,s] . wv

// ---------------- helpers ----------------
__device__ __forceinline__ uint32_t f2tf(float x) {
    uint32_t u;
    asm("cvt.rna.tf32.f32 %0, %1;" : "=r"(u) : "f"(x));
    return u;
}

__device__ __forceinline__ void mma8(float c[4], const uint32_t a[4], const uint32_t b[2]) {
    asm volatile(
        "mma.sync.aligned.m16n8k8.row.col.f32.tf32.tf32.f32 "
        "{%0,%1,%2,%3}, {%4,%5,%6,%7}, {%8,%9}, {%0,%1,%2,%3};"
        : "+f"(c[0]), "+f"(c[1]), "+f"(c[2]), "+f"(c[3])
        : "r"(a[0]), "r"(a[1]), "r"(a[2]), "r"(a[3]), "r"(b[0]), "r"(b[1]));
}

__device__ __forceinline__ void cpa16(float* dst_smem, const float* src) {
    uint32_t d = (uint32_t)__cvta_generic_to_shared(dst_smem);
    asm volatile("cp.async.cg.shared.global [%0], [%1], 16;" :: "r"(d), "l"(src));
}

// ---------------- K1: Wc^T and wv ----------------
__global__ __launch_bounds__(D) void k_prep(const float* __restrict__ Wq,
                                            const float* __restrict__ Wk,
                                            const float* __restrict__ bq) {
    int n = blockIdx.x;
    int k = threadIdx.x;
    float acc = 0.f;
    for (int i = 0; i < D; ++i)
        acc = fmaf(Wq[i * D + k], Wk[i * D + n], acc);
    g_WcT[n * D + k] = acc;

    __shared__ float red[D];
    red[k] = bq[k] * Wk[k * D + n];
    __syncthreads();
    for (int s = D / 2; s > 0; s >>= 1) {
        if (k < s) red[k] += red[k + s];
        __syncthreads();
    }
    if (k == 0) g_wv[n] = red[0];
}

// ---------------- K_v: v[b,s] = F_s[b,s] . wv ----------------
__global__ __launch_bounds__(256) void k_v(const float* __restrict__ F_s) {
    __shared__ float swv[D];
    int tid = threadIdx.x;
    swv[tid] = g_wv[tid];
    __syncthreads();
    int r = blockIdx.x * 32 + (tid >> 3);
    int l8 = tid & 7;
    const float4* row = reinterpret_cast<const float4*>(F_s + (size_t)r * D);
    const float4* wv4 = reinterpret_cast<const float4*>(swv);
    float s = 0.f;
#pragma unroll
    for (int q = 0; q < 8; ++q) {
        float4 f = row[l8 * 8 + q];
        float4 w = wv4[l8 * 8 + q];
        s += f.x * w.x + f.y * w.y + f.z * w.z + f.w * w.w;
    }
    s += __shfl_down_sync(0xffffffffu, s, 4, 8);
    s += __shfl_down_sync(0xffffffffu, s, 2, 8);
    s += __shfl_down_sync(0xffffffffu, s, 1, 8);
    if (l8 == 0) g_v[r] = s;
}

// ---------------- small split-tf32 GEMM for G (fp32-quality) ----------------
// 128x128 tile, 256 threads, warp 32x64, split A and B (3 mma terms).
__global__ __launch_bounds__(256) void gemm_g(
    const float* __restrict__ A0, const float* __restrict__ B0, float* __restrict__ C0) {
    extern __shared__ uint32_t sm[];
    uint32_t* Ah = sm;
    uint32_t* Al = Ah + 128 * LDSW;
    uint32_t* Bh = Ah + 2 * 128 * LDSW;
    uint32_t* Bl = Bh + 128 * LDSW;

    int m0 = blockIdx.y * 128;
    int n0 = blockIdx.x * 128;
    const float* A = A0 + (size_t)m0 * D;
    const float* B = B0 + (size_t)n0 * D;

    int tid = threadIdx.x;
    int lane = tid & 31, wid = tid >> 5;
    int g = lane >> 2, tg = lane & 3;
    int wm = (wid & 3) * 32;
    int wn = (wid >> 2) * 64;

    float acc[2][8][4];
#pragma unroll
    for (int i = 0; i < 2; ++i)
#pragma unroll
        for (int j = 0; j < 8; ++j)
#pragma unroll
            for (int c = 0; c < 4; ++c) acc[i][j][c] = 0.f;

    for (int k0 = 0; k0 < D; k0 += BKK) {
#pragma unroll
        for (int q = 0; q < 2; ++q) {
            int idx = tid + 256 * q;
            int row = idx >> 2;
            int c4 = (idx & 3) * 4;
            float4 xa = *reinterpret_cast<const float4*>(A + (size_t)row * D + k0 + c4);
            float4 xb = *reinterpret_cast<const float4*>(B + (size_t)row * D + k0 + c4);
            float va[4] = {xa.x, xa.y, xa.z, xa.w};
            float vb[4] = {xb.x, xb.y, xb.z, xb.w};
#pragma unroll
            for (int j = 0; j < 4; ++j) {
                uint32_t h = f2tf(va[j]);
                Ah[row * LDSW + c4 + j] = h;
                Al[row * LDSW + c4 + j] = f2tf(va[j] - __uint_as_float(h));
                uint32_t hb = f2tf(vb[j]);
                Bh[row * LDSW + c4 + j] = hb;
                Bl[row * LDSW + c4 + j] = f2tf(vb[j] - __uint_as_float(hb));
            }
        }
        __syncthreads();
#pragma unroll
        for (int kk = 0; kk < BKK; kk += 8) {
            uint32_t ah[2][4], al[2][4], bh[8][2], bl[8][2];
#pragma unroll
            for (int mi = 0; mi < 2; ++mi) {
                int r = wm + mi * 16;
                ah[mi][0] = Ah[(r + g) * LDSW + kk + tg];
                ah[mi][1] = Ah[(r + g + 8) * LDSW + kk + tg];
                ah[mi][2] = Ah[(r + g) * LDSW + kk + tg + 4];
                ah[mi][3] = Ah[(r + g + 8) * LDSW + kk + tg + 4];
                al[mi][0] = Al[(r + g) * LDSW + kk + tg];
                al[mi][1] = Al[(r + g + 8) * LDSW + kk + tg];
                al[mi][2] = Al[(r + g) * LDSW + kk + tg + 4];
                al[mi][3] = Al[(r + g + 8) * LDSW + kk + tg + 4];
            }
#pragma unroll
            for (int ni = 0; ni < 8; ++ni) {
                int r = wn + ni * 8 + g;
                bh[ni][0] = Bh[r * LDSW + kk + tg];
                bh[ni][1] = Bh[r * LDSW + kk + tg + 4];
                bl[ni][0] = Bl[r * LDSW + kk + tg];
                bl[ni][1] = Bl[r * LDSW + kk + tg + 4];
            }
#pragma unroll
            for (int mi = 0; mi < 2; ++mi)
#pragma unroll
                for (int ni = 0; ni < 8; ++ni) {
                    mma8(acc[mi][ni], ah[mi], bh[ni]);
                    mma8(acc[mi][ni], al[mi], bh[ni]);
                    mma8(acc[mi][ni], ah[mi], bl[ni]);
                }
        }
        __syncthreads();
    }

#pragma unroll
    for (int mi = 0; mi < 2; ++mi)
#pragma unroll
        for (int h = 0; h < 2; ++h) {
            int row = m0 + wm + mi * 16 + g + h * 8;
#pragma unroll
            for (int ni = 0; ni < 8; ++ni) {
                int col = n0 + wn + ni * 8 + 2 * tg;
                *reinterpret_cast<float2*>(C0 + (size_t)row * D + col) =
                    make_float2(acc[mi][ni][h * 2 + 0], acc[mi][ni][h * 2 + 1]);
            }
        }
}

// ---------------- big logits GEMM: out = mask((G @ F_s^T + v)/16) ----------------
// CTA tile 128x256, 8 warps (2x4), warp tile 64x64. Single-pass tf32.
// cp.async double-buffered, BKL=16, LDB=20 (conflict-free fragment loads).
#define BKL 16
#define LDB 20

__global__ __launch_bounds__(256) void gemm_big(
    const float* __restrict__ G0, const float* __restrict__ Fs,
    float* __restrict__ Out, const float* __restrict__ v0,
    const int* __restrict__ msk0) {
    extern __shared__ float smf[];
    float* As = smf;                    // [2][128*LDB]
    float* Bs = smf + 2 * 128 * LDB;    // [2][256*LDB]

    int z = blockIdx.z;
    int m0 = blockIdx.y * 128;
    int n0 = blockIdx.x * 256;
    const float* A = G0 + (size_t)z * 256 * D + (size_t)m0 * D;
    const float* B = Fs + (size_t)z * 4096 * D + (size_t)n0 * D;

    int tid = threadIdx.x;
    int lane = tid & 31, wid = tid >> 5;
    int g = lane >> 2, tg = lane & 3;
    int wm = (wid & 1) * 64;
    int wn = (wid >> 1) * 64;

    float acc[4][8][4];
#pragma unroll
    for (int i = 0; i < 4; ++i)
#pragma unroll
        for (int j = 0; j < 8; ++j)
#pragma unroll
            for (int c = 0; c < 4; ++c) acc[i][j][c] = 0.f;

    int arow = tid >> 2;            // 0..63 (+64 in second A chunk)
    int ac4 = (tid & 3) * 4;

    // prologue: stage 0
    {
        float* Ad = As;
        float* Bd = Bs;
#pragma unroll
        for (int q = 0; q < 2; ++q) {
            int row = arow + q * 64;
            cpa16(Ad + row * LDB + ac4, A + (size_t)row * D + ac4);
        }
#pragma unroll
        for (int q = 0; q < 4; ++q) {
            int row = arow + q * 64;
            cpa16(Bd + row * LDB + ac4, B + (size_t)row * D + ac4);
        }
        asm volatile("cp.async.commit_group;");
    }

    const int NT = D / BKL;  // 16
    for (int t = 0; t < NT; ++t) {
        int st = t & 1;
        if (t + 1 < NT) {
            int k0 = (t + 1) * BKL;
            float* Ad = As + (st ^ 1) * 128 * LDB;
            float* Bd = Bs + (st ^ 1) * 256 * LDB;
#pragma unroll
            for (int q = 0; q < 2; ++q) {
                int row = arow + q * 64;
                cpa16(Ad + row * LDB + ac4, A + (size_t)row * D + k0 + ac4);
            }
#pragma unroll
            for (int q = 0; q < 4; ++q) {
                int row = arow + q * 64;
                cpa16(Bd + row * LDB + ac4, B + (size_t)row * D + k0 + ac4);
            }
            asm volatile("cp.async.commit_group;");
            asm volatile("cp.async.wait_group 1;");
        } else {
            asm volatile("cp.async.wait_group 0;");
        }
        __syncthreads();

        const float* Aa = As + st * 128 * LDB;
        const float* Bb = Bs + st * 256 * LDB;
#pragma unroll
        for (int kk = 0; kk < BKL; kk += 8) {
            uint32_t af[4][4], bf[8][2];
#pragma unroll
            for (int mi = 0; mi < 4; ++mi) {
                int r = wm + mi * 16 + g;
                af[mi][0] = f2tf(Aa[r * LDB + kk + tg]);
                af[mi][1] = f2tf(Aa[(r + 8) * LDB + kk + tg]);
                af[mi][2] = f2tf(Aa[r * LDB + kk + tg + 4]);
                af[mi][3] = f2tf(Aa[(r + 8) * LDB + kk + tg + 4]);
            }
#pragma unroll
            for (int ni = 0; ni < 8; ++ni) {
                int r = wn + ni * 8 + g;
                bf[ni][0] = f2tf(Bb[r * LDB + kk + tg]);
                bf[ni][1] = f2tf(Bb[r * LDB + kk + tg + 4]);
            }
#pragma unroll
            for (int mi = 0; mi < 4; ++mi)
#pragma unroll
                for (int ni = 0; ni < 8; ++ni)
                    mma8(acc[mi][ni], af[mi], bf[ni]);
        }
        __syncthreads();
    }

    // epilogue: +v, /16, mask, store
    const float* v = v0 + (size_t)z * 4096;
    const int* mk = msk0 + (size_t)z * 4096;
    float* C = Out + (size_t)z * 256 * 4096;
#pragma unroll
    for (int mi = 0; mi < 4; ++mi)
#pragma unroll
        for (int h = 0; h < 2; ++h) {
            int row = m0 + wm + mi * 16 + g + h * 8;
#pragma unroll
            for (int ni = 0; ni < 8; ++ni) {
                int col = n0 + wn + ni * 8 + 2 * tg;
                float y0 = (acc[mi][ni][h * 2 + 0] + v[col]) * 0.0625f;
                float y1 = (acc[mi][ni][h * 2 + 1] + v[col + 1]) * 0.0625f;
                if (mk[col] == 0) y0 = -1e30f;
                if (mk[col + 1] == 0) y1 = -1e30f;
                *reinterpret_cast<float2*>(C + (size_t)row * 4096 + col) = make_float2(y0, y1);
            }
        }
}

// ---------------- softmax over rows of 4096 (in-place on d_out) ----------------
__global__ __launch_bounds__(256) void k_softmax(float* __restrict__ Out) {
    size_t row = blockIdx.x;
    float* p = Out + row * 4096;
    int tid = threadIdx.x;
    float4 x[4];
#pragma unroll
    for (int q = 0; q < 4; ++q) x[q] = reinterpret_cast<float4*>(p)[tid + 256 * q];

    float mx = -3.0e38f;
#pragma unroll
    for (int q = 0; q < 4; ++q)
        mx = fmaxf(mx, fmaxf(fmaxf(x[q].x, x[q].y), fmaxf(x[q].z, x[q].w)));

    __shared__ float red[8];
    __shared__ float bc;
#pragma unroll
    for (int o = 16; o > 0; o >>= 1) mx = fmaxf(mx, __shfl_xor_sync(0xffffffffu, mx, o));
    if ((tid & 31) == 0) red[tid >> 5] = mx;
    __syncthreads();
    if (tid < 32) {
        float t = (tid < 8) ? red[tid] : -3.0e38f;
#pragma unroll
        for (int o = 4; o > 0; o >>= 1) t = fmaxf(t, __shfl_xor_sync(0xffffffffu, t, o));
        if (tid == 0) bc = t;
    }
    __syncthreads();
    mx = bc;

    float sum = 0.f;
#pragma unroll
    for (int q = 0; q < 4; ++q) {
        x[q].x = __expf(x[q].x - mx); sum += x[q].x;
        x[q].y = __expf(x[q].y - mx); sum += x[q].y;
        x[q].z = __expf(x[q].z - mx); sum += x[q].z;
        x[q].w = __expf(x[q].w - mx); sum += x[q].w;
    }
#pragma unroll
    for (int o = 16; o > 0; o >>= 1) sum += __shfl_xor_sync(0xffffffffu, sum, o);
    __syncthreads();
    if ((tid & 31) == 0) red[tid >> 5] = sum;
    __syncthreads();
    if (tid < 32) {
        float t = (tid < 8) ? red[tid] : 0.f;
#pragma unroll
        for (int o = 4; o > 0; o >>= 1) t += __shfl_xor_sync(0xffffffffu, t, o);
        if (tid == 0) bc = t;
    }
    __syncthreads();
    float inv = 1.0f / bc;
#pragma unroll
    for (int q = 0; q < 4; ++q) {
        x[q].x *= inv; x[q].y *= inv; x[q].z *= inv; x[q].w *= inv;
        reinterpret_cast<float4*>(p)[tid + 256 * q] = x[q];
    }
}

// ---------------- launch ----------------
extern "C" void kernel_launch(void* const* d_in, const int* in_sizes, int n_in,
                              void* d_out, int out_size) {
    const float* F_a = (const float*)d_in[0];
    const float* F_s = (const float*)d_in[1];
    const int*   M_s = (const int*)d_in[2];
    const float* Wq  = (const float*)d_in[3];
    const float* bq  = (const float*)d_in[4];
    const float* Wk  = (const float*)d_in[5];
    // d_in[6] (bk) contributes only per-row constants -> cancels in softmax.
    float* out = (float*)d_out;

    void *p0 = nullptr, *p1 = nullptr, *p2 = nullptr;
    cudaGetSymbolAddress(&p0, g_WcT);
    cudaGetSymbolAddress(&p1, g_G);
    cudaGetSymbolAddress(&p2, g_v);
    float* pWcT = (float*)p0;
    float* pG = (float*)p1;
    float* pV = (float*)p2;

    const int smem_g   = 4 * 128 * LDSW * 4;            // 34816 B (<48K)
    const int smem_big = (2 * 128 + 2 * 256) * LDB * 4; // 61440 B (>48K)
    cudaFuncSetAttribute(gemm_big, cudaFuncAttributeMaxDynamicSharedMemorySize, smem_big);

    // 1) Wc^T = (Wq^T Wk)^T and wv = Wk^T bq
    k_prep<<<D, D>>>(Wq, Wk, bq);

    // 2) G = F_a @ Wc   (M=8192, N=256, K=256), full split -> fp32-quality
    gemm_g<<<dim3(2, 64, 1), 256, smem_g>>>(F_a, pWcT, pG);

    // 3) v[b,s] = F_s[b,s] . wv
    k_v<<<4096, 256>>>(F_s);

    // 4) logits = (G @ F_s^T + v)/16, masked; written to d_out
    gemm_big<<<dim3(16, 2, 32), 256, smem_big>>>(pG, F_s, out, pV, M_s);

    // 5) row softmax in place
    k_softmax<<<32 * 256, 256>>>(out);
}

// round 7
// speedup vs baseline: 1.4042x; 1.0472x over previous
#include <cuda_runtime.h>
#include <cstdint>
#include <cstddef>

#define D 256
#define BKK 16
#define LDSW (BKK + 1)

// ---------------- device scratch (no allocations allowed) ----------------
__device__ float g_WcT[D * D];        // WcT[n][k] = sum_i Wq[i][k]*Wk[i][n]
__device__ float g_wv[D];             // wv[l] = sum_i bq[i]*Wk[i][l]
__device__ float g_G[32 * 256 * D];   // G = F_a @ Wc   [B*T, D]
__device__ float g_v[32 * 4096];      // v[b,s] = F_s[b,s] . wv

// ---------------- helpers ----------------
__device__ __forceinline__ uint32_t f2tf(float x) {
    uint32_t u;
    asm("cvt.rna.tf32.f32 %0, %1;" : "=r"(u) : "f"(x));
    return u;
}

__device__ __forceinline__ void mma8(float c[4], const uint32_t a[4], const uint32_t b[2]) {
    asm volatile(
        "mma.sync.aligned.m16n8k8.row.col.f32.tf32.tf32.f32 "
        "{%0,%1,%2,%3}, {%4,%5,%6,%7}, {%8,%9}, {%0,%1,%2,%3};"
        : "+f"(c[0]), "+f"(c[1]), "+f"(c[2]), "+f"(c[3])
        : "r"(a[0]), "r"(a[1]), "r"(a[2]), "r"(a[3]), "r"(b[0]), "r"(b[1]));
}

__device__ __forceinline__ void cpa16(float* dst_smem, const float* src) {
    uint32_t d = (uint32_t)__cvta_generic_to_shared(dst_smem);
    asm volatile("cp.async.cg.shared.global [%0], [%1], 16;" :: "r"(d), "l"(src));
}

// ---------------- K1: Wc^T and wv ----------------
__global__ __launch_bounds__(D) void k_prep(const float* __restrict__ Wq,
                                            const float* __restrict__ Wk,
                                            const float* __restrict__ bq) {
    int n = blockIdx.x;
    int k = threadIdx.x;
    float acc = 0.f;
    for (int i = 0; i < D; ++i)
        acc = fmaf(Wq[i * D + k], Wk[i * D + n], acc);
    g_WcT[n * D + k] = acc;

    __shared__ float red[D];
    red[k] = bq[k] * Wk[k * D + n];
    __syncthreads();
    for (int s = D / 2; s > 0; s >>= 1) {
        if (k < s) red[k] += red[k + s];
        __syncthreads();
    }
    if (k == 0) g_wv[n] = red[0];
}

// ---------------- K_v: v[b,s] = F_s[b,s] . wv ----------------
__global__ __launch_bounds__(256) void k_v(const float* __restrict__ F_s) {
    __shared__ float swv[D];
    int tid = threadIdx.x;
    swv[tid] = g_wv[tid];
    __syncthreads();
    int r = blockIdx.x * 32 + (tid >> 3);
    int l8 = tid & 7;
    const float4* row = reinterpret_cast<const float4*>(F_s + (size_t)r * D);
    const float4* wv4 = reinterpret_cast<const float4*>(swv);
    float s = 0.f;
#pragma unroll
    for (int q = 0; q < 8; ++q) {
        float4 f = row[l8 * 8 + q];
        float4 w = wv4[l8 * 8 + q];
        s += f.x * w.x + f.y * w.y + f.z * w.z + f.w * w.w;
    }
    s += __shfl_down_sync(0xffffffffu, s, 4, 8);
    s += __shfl_down_sync(0xffffffffu, s, 2, 8);
    s += __shfl_down_sync(0xffffffffu, s, 1, 8);
    if (l8 == 0) g_v[r] = s;
}

// ---------------- small split-tf32 GEMM for G (fp32-quality) ----------------
__global__ __launch_bounds__(256) void gemm_g(
    const float* __restrict__ A0, const float* __restrict__ B0, float* __restrict__ C0) {
    extern __shared__ uint32_t sm[];
    uint32_t* Ah = sm;
    uint32_t* Al = Ah + 128 * LDSW;
    uint32_t* Bh = Ah + 2 * 128 * LDSW;
    uint32_t* Bl = Bh + 128 * LDSW;

    int m0 = blockIdx.y * 128;
    int n0 = blockIdx.x * 128;
    const float* A = A0 + (size_t)m0 * D;
    const float* B = B0 + (size_t)n0 * D;

    int tid = threadIdx.x;
    int lane = tid & 31, wid = tid >> 5;
    int g = lane >> 2, tg = lane & 3;
    int wm = (wid & 3) * 32;
    int wn = (wid >> 2) * 64;

    float acc[2][8][4];
#pragma unroll
    for (int i = 0; i < 2; ++i)
#pragma unroll
        for (int j = 0; j < 8; ++j)
#pragma unroll
            for (int c = 0; c < 4; ++c) acc[i][j][c] = 0.f;

    for (int k0 = 0; k0 < D; k0 += BKK) {
#pragma unroll
        for (int q = 0; q < 2; ++q) {
            int idx = tid + 256 * q;
            int row = idx >> 2;
            int c4 = (idx & 3) * 4;
            float4 xa = *reinterpret_cast<const float4*>(A + (size_t)row * D + k0 + c4);
            float4 xb = *reinterpret_cast<const float4*>(B + (size_t)row * D + k0 + c4);
            float va[4] = {xa.x, xa.y, xa.z, xa.w};
            float vb[4] = {xb.x, xb.y, xb.z, xb.w};
#pragma unroll
            for (int j = 0; j < 4; ++j) {
                uint32_t h = f2tf(va[j]);
                Ah[row * LDSW + c4 + j] = h;
                Al[row * LDSW + c4 + j] = f2tf(va[j] - __uint_as_float(h));
                uint32_t hb = f2tf(vb[j]);
                Bh[row * LDSW + c4 + j] = hb;
                Bl[row * LDSW + c4 + j] = f2tf(vb[j] - __uint_as_float(hb));
            }
        }
        __syncthreads();
#pragma unroll
        for (int kk = 0; kk < BKK; kk += 8) {
            uint32_t ah[2][4], al[2][4], bh[8][2], bl[8][2];
#pragma unroll
            for (int mi = 0; mi < 2; ++mi) {
                int r = wm + mi * 16;
                ah[mi][0] = Ah[(r + g) * LDSW + kk + tg];
                ah[mi][1] = Ah[(r + g + 8) * LDSW + kk + tg];
                ah[mi][2] = Ah[(r + g) * LDSW + kk + tg + 4];
                ah[mi][3] = Ah[(r + g + 8) * LDSW + kk + tg + 4];
                al[mi][0] = Al[(r + g) * LDSW + kk + tg];
                al[mi][1] = Al[(r + g + 8) * LDSW + kk + tg];
                al[mi][2] = Al[(r + g) * LDSW + kk + tg + 4];
                al[mi][3] = Al[(r + g + 8) * LDSW + kk + tg + 4];
            }
#pragma unroll
            for (int ni = 0; ni < 8; ++ni) {
                int r = wn + ni * 8 + g;
                bh[ni][0] = Bh[r * LDSW + kk + tg];
                bh[ni][1] = Bh[r * LDSW + kk + tg + 4];
                bl[ni][0] = Bl[r * LDSW + kk + tg];
                bl[ni][1] = Bl[r * LDSW + kk + tg + 4];
            }
#pragma unroll
            for (int mi = 0; mi < 2; ++mi)
#pragma unroll
                for (int ni = 0; ni < 8; ++ni) {
                    mma8(acc[mi][ni], ah[mi], bh[ni]);
                    mma8(acc[mi][ni], al[mi], bh[ni]);
                    mma8(acc[mi][ni], ah[mi], bl[ni]);
                }
        }
        __syncthreads();
    }

#pragma unroll
    for (int mi = 0; mi < 2; ++mi)
#pragma unroll
        for (int h = 0; h < 2; ++h) {
            int row = m0 + wm + mi * 16 + g + h * 8;
#pragma unroll
            for (int ni = 0; ni < 8; ++ni) {
                int col = n0 + wn + ni * 8 + 2 * tg;
                *reinterpret_cast<float2*>(C0 + (size_t)row * D + col) =
                    make_float2(acc[mi][ni][h * 2 + 0], acc[mi][ni][h * 2 + 1]);
            }
        }
}

// ---------------- big logits GEMM: out = mask((G @ F_s^T + v)/16) ----------------
// CTA tile 128x256, 8 warps (2x4), warp tile 64x64. Single-pass tf32.
// BKL=32, LDB=36 (conflict-free), cp.async double buffer,
// register double-buffered fragments (LDS/cvt for kk+8 overlap mma of kk).
#define BKL 32
#define LDB 36

__global__ __launch_bounds__(256) void gemm_big(
    const float* __restrict__ G0, const float* __restrict__ Fs,
    float* __restrict__ Out, const float* __restrict__ v0,
    const int* __restrict__ msk0) {
    extern __shared__ float smf[];
    float* As = smf;                    // [2][128*LDB]
    float* Bs = smf + 2 * 128 * LDB;    // [2][256*LDB]

    int z = blockIdx.z;
    int m0 = blockIdx.y * 128;
    int n0 = blockIdx.x * 256;
    const float* A = G0 + (size_t)z * 256 * D + (size_t)m0 * D;
    const float* B = Fs + (size_t)z * 4096 * D + (size_t)n0 * D;

    int tid = threadIdx.x;
    int lane = tid & 31, wid = tid >> 5;
    int g = lane >> 2, tg = lane & 3;
    int wm = (wid & 1) * 64;
    int wn = (wid >> 1) * 64;

    float acc[4][8][4];
#pragma unroll
    for (int i = 0; i < 4; ++i)
#pragma unroll
        for (int j = 0; j < 8; ++j)
#pragma unroll
            for (int c = 0; c < 4; ++c) acc[i][j][c] = 0.f;

    int arow = tid >> 3;            // 0..31
    int ac4 = (tid & 7) * 4;        // 0..28

    // prologue: stage 0
    {
#pragma unroll
        for (int q = 0; q < 4; ++q) {
            int row = arow + q * 32;
            cpa16(As + row * LDB + ac4, A + (size_t)row * D + ac4);
        }
#pragma unroll
        for (int q = 0; q < 8; ++q) {
            int row = arow + q * 32;
            cpa16(Bs + row * LDB + ac4, B + (size_t)row * D + ac4);
        }
        asm volatile("cp.async.commit_group;");
    }

    uint32_t af[2][4][4], bf[2][8][2];

    const int NT = D / BKL;  // 8
    for (int t = 0; t < NT; ++t) {
        int st = t & 1;
        if (t + 1 < NT) {
            int k0 = (t + 1) * BKL;
            float* Ad = As + (st ^ 1) * 128 * LDB;
            float* Bd = Bs + (st ^ 1) * 256 * LDB;
#pragma unroll
            for (int q = 0; q < 4; ++q) {
                int row = arow + q * 32;
                cpa16(Ad + row * LDB + ac4, A + (size_t)row * D + k0 + ac4);
            }
#pragma unroll
            for (int q = 0; q < 8; ++q) {
                int row = arow + q * 32;
                cpa16(Bd + row * LDB + ac4, B + (size_t)row * D + k0 + ac4);
            }
            asm volatile("cp.async.commit_group;");
            asm volatile("cp.async.wait_group 1;");
        } else {
            asm volatile("cp.async.wait_group 0;");
        }
        __syncthreads();

        const float* Aa = As + st * 128 * LDB;
        const float* Bb = Bs + st * 256 * LDB;

        // load fragments for kk = 0 into buffer 0
#pragma unroll
        for (int mi = 0; mi < 4; ++mi) {
            int r = wm + mi * 16 + g;
            af[0][mi][0] = f2tf(Aa[r * LDB + tg]);
            af[0][mi][1] = f2tf(Aa[(r + 8) * LDB + tg]);
            af[0][mi][2] = f2tf(Aa[r * LDB + tg + 4]);
            af[0][mi][3] = f2tf(Aa[(r + 8) * LDB + tg + 4]);
        }
#pragma unroll
        for (int ni = 0; ni < 8; ++ni) {
            int r = wn + ni * 8 + g;
            bf[0][ni][0] = f2tf(Bb[r * LDB + tg]);
            bf[0][ni][1] = f2tf(Bb[r * LDB + tg + 4]);
        }

#pragma unroll
        for (int s8 = 0; s8 < 4; ++s8) {
            int p = s8 & 1;
            int pn = p ^ 1;
            if (s8 < 3) {
                int kk = (s8 + 1) * 8;
#pragma unroll
                for (int mi = 0; mi < 4; ++mi) {
                    int r = wm + mi * 16 + g;
                    af[pn][mi][0] = f2tf(Aa[r * LDB + kk + tg]);
                    af[pn][mi][1] = f2tf(Aa[(r + 8) * LDB + kk + tg]);
                    af[pn][mi][2] = f2tf(Aa[r * LDB + kk + tg + 4]);
                    af[pn][mi][3] = f2tf(Aa[(r + 8) * LDB + kk + tg + 4]);
                }
#pragma unroll
                for (int ni = 0; ni < 8; ++ni) {
                    int r = wn + ni * 8 + g;
                    bf[pn][ni][0] = f2tf(Bb[r * LDB + kk + tg]);
                    bf[pn][ni][1] = f2tf(Bb[r * LDB + kk + tg + 4]);
                }
            }
#pragma unroll
            for (int mi = 0; mi < 4; ++mi)
#pragma unroll
                for (int ni = 0; ni < 8; ++ni)
                    mma8(acc[mi][ni], af[p][mi], bf[p][ni]);
        }
        __syncthreads();
    }

    // epilogue: +v, /16, mask, store
    const float* v = v0 + (size_t)z * 4096;
    const int* mk = msk0 + (size_t)z * 4096;
    float* C = Out + (size_t)z * 256 * 4096;
#pragma unroll
    for (int mi = 0; mi < 4; ++mi)
#pragma unroll
        for (int h = 0; h < 2; ++h) {
            int row = m0 + wm + mi * 16 + g + h * 8;
#pragma unroll
            for (int ni = 0; ni < 8; ++ni) {
                int col = n0 + wn + ni * 8 + 2 * tg;
                float y0 = (acc[mi][ni][h * 2 + 0] + v[col]) * 0.0625f;
                float y1 = (acc[mi][ni][h * 2 + 1] + v[col + 1]) * 0.0625f;
                if (mk[col] == 0) y0 = -1e30f;
                if (mk[col + 1] == 0) y1 = -1e30f;
                *reinterpret_cast<float2*>(C + (size_t)row * 4096 + col) = make_float2(y0, y1);
            }
        }
}

// ---------------- softmax over rows of 4096 (in-place on d_out) ----------------
__global__ __launch_bounds__(256) void k_softmax(float* __restrict__ Out) {
    size_t row = blockIdx.x;
    float* p = Out + row * 4096;
    int tid = threadIdx.x;
    float4 x[4];
#pragma unroll
    for (int q = 0; q < 4; ++q) x[q] = reinterpret_cast<float4*>(p)[tid + 256 * q];

    float mx = -3.0e38f;
#pragma unroll
    for (int q = 0; q < 4; ++q)
        mx = fmaxf(mx, fmaxf(fmaxf(x[q].x, x[q].y), fmaxf(x[q].z, x[q].w)));

    __shared__ float red[8];
    __shared__ float bc;
#pragma unroll
    for (int o = 16; o > 0; o >>= 1) mx = fmaxf(mx, __shfl_xor_sync(0xffffffffu, mx, o));
    if ((tid & 31) == 0) red[tid >> 5] = mx;
    __syncthreads();
    if (tid < 32) {
        float t = (tid < 8) ? red[tid] : -3.0e38f;
#pragma unroll
        for (int o = 4; o > 0; o >>= 1) t = fmaxf(t, __shfl_xor_sync(0xffffffffu, t, o));
        if (tid == 0) bc = t;
    }
    __syncthreads();
    mx = bc;

    float sum = 0.f;
#pragma unroll
    for (int q = 0; q < 4; ++q) {
        x[q].x = __expf(x[q].x - mx); sum += x[q].x;
        x[q].y = __expf(x[q].y - mx); sum += x[q].y;
        x[q].z = __expf(x[q].z - mx); sum += x[q].z;
        x[q].w = __expf(x[q].w - mx); sum += x[q].w;
    }
#pragma unroll
    for (int o = 16; o > 0; o >>= 1) sum += __shfl_xor_sync(0xffffffffu, sum, o);
    __syncthreads();
    if ((tid & 31) == 0) red[tid >> 5] = sum;
    __syncthreads();
    if (tid < 32) {
        float t = (tid < 8) ? red[tid] : 0.f;
#pragma unroll
        for (int o = 4; o > 0; o >>= 1) t += __shfl_xor_sync(0xffffffffu, t, o);
        if (tid == 0) bc = t;
    }
    __syncthreads();
    float inv = 1.0f / bc;
#pragma unroll
    for (int q = 0; q < 4; ++q) {
        x[q].x *= inv; x[q].y *= inv; x[q].z *= inv; x[q].w *= inv;
        reinterpret_cast<float4*>(p)[tid + 256 * q] = x[q];
    }
}

// ---------------- launch ----------------
extern "C" void kernel_launch(void* const* d_in, const int* in_sizes, int n_in,
                              void* d_out, int out_size) {
    const float* F_a = (const float*)d_in[0];
    const float* F_s = (const float*)d_in[1];
    const int*   M_s = (const int*)d_in[2];
    const float* Wq  = (const float*)d_in[3];
    const float* bq  = (const float*)d_in[4];
    const float* Wk  = (const float*)d_in[5];
    // d_in[6] (bk) contributes only per-row constants -> cancels in softmax.
    float* out = (float*)d_out;

    void *p0 = nullptr, *p1 = nullptr, *p2 = nullptr;
    cudaGetSymbolAddress(&p0, g_WcT);
    cudaGetSymbolAddress(&p1, g_G);
    cudaGetSymbolAddress(&p2, g_v);
    float* pWcT = (float*)p0;
    float* pG = (float*)p1;
    float* pV = (float*)p2;

    const int smem_g   = 4 * 128 * LDSW * 4;                  // 34816 B (<48K)
    const int smem_big = (2 * 128 + 2 * 256) * LDB * 4;       // 110592 B (>48K)
    cudaFuncSetAttribute(gemm_big, cudaFuncAttributeMaxDynamicSharedMemorySize, smem_big);

    // 1) Wc^T = (Wq^T Wk)^T and wv = Wk^T bq
    k_prep<<<D, D>>>(Wq, Wk, bq);

    // 2) G = F_a @ Wc   (M=8192, N=256, K=256), full split -> fp32-quality
    gemm_g<<<dim3(2, 64, 1), 256, smem_g>>>(F_a, pWcT, pG);

    // 3) v[b,s] = F_s[b,s] . wv
    k_v<<<4096, 256>>>(F_s);

    // 4) logits = (G @ F_s^T + v)/16, masked; written to d_out
    gemm_big<<<dim3(16, 2, 32), 256, smem_big>>>(pG, F_s, out, pV, M_s);

    // 5) row softmax in place
    k_softmax<<<32 * 256, 256>>>(out);
}